// round 1
// baseline (speedup 1.0000x reference)
#include <cuda_runtime.h>
#include <cuda_bf16.h>

// Problem constants: activation (N=32, C=16, H=224, W=224) float32.
// Per-channel block sizes: c0-1 identity, c2-3 (1,1), c4-7 (2,2), c8-11 (4,4), c12-15 (3,3).
#define N_ 32
#define C_ 16
#define H_ 224
#define W_ 224
#define BAND 12   // lcm(1,2,3,4): every band start aligns with every block size

__constant__ int d_bh[C_] = {0, 0, 1, 1, 2, 2, 2, 2, 4, 4, 4, 4, 3, 3, 3, 3};

__global__ __launch_bounds__(224) void block_relu_kernel(
    const float* __restrict__ in, float* __restrict__ out)
{
    __shared__ float colsum[W_];

    const int c    = blockIdx.y;
    const int n    = blockIdx.z;
    const int row0 = blockIdx.x * BAND;
    const int rows = min(BAND, H_ - row0);
    const int tid  = threadIdx.x;   // 0..223

    const size_t img = ((size_t)(n * C_ + c)) * H_ * W_;
    const float* __restrict__ src = in  + img;
    float*       __restrict__ dst = out + img;

    const int bh = d_bh[c];

    if (bh <= 1) {
        // identity (bh==0) or elementwise sign-relu (bh==1)
        const int total = rows * W_;
        const float* s = src + (size_t)row0 * W_;
        float*       d = dst + (size_t)row0 * W_;
        if (bh == 0) {
            for (int i = tid; i < total; i += 224) d[i] = s[i];
        } else {
            for (int i = tid; i < total; i += 224) {
                float v = s[i];
                d[i] = (v >= 0.0f) ? v : 0.0f;
            }
        }
        return;
    }

    // Block path: bh == bw in {2,3,4}. Thread tid owns column tid.
    const int x   = tid;
    const int nbr = BAND / bh;           // block-rows per band (bh=3 -> 4, with break)

    for (int br = 0; br < nbr; br++) {
        const int r0 = row0 + br * bh;
        if (r0 >= H_) break;             // uniform across CTA

        float v[4];
        float cs = 0.0f;
        #pragma unroll
        for (int j = 0; j < 4; j++) {
            if (j < bh) {
                const int r = r0 + j;
                v[j] = (r < H_) ? src[(size_t)r * W_ + x] : 0.0f;  // zero-pad bottom
                cs += v[j];
            }
        }
        colsum[x] = cs;
        __syncthreads();

        const int start = (x / bh) * bh;
        float s = 0.0f;
        #pragma unroll
        for (int k = 0; k < 4; k++) {
            if (k < bh) {
                const int cc = start + k;
                if (cc < W_) s += colsum[cc];   // zero-pad right edge (3x3 group)
            }
        }
        const float m = (s >= 0.0f) ? 1.0f : 0.0f;

        #pragma unroll
        for (int j = 0; j < 4; j++) {
            if (j < bh) {
                const int r = r0 + j;
                if (r < H_) dst[(size_t)r * W_ + x] = v[j] * m;
            }
        }
        __syncthreads();   // protect colsum for next block-row
    }
}

extern "C" void kernel_launch(void* const* d_in, const int* in_sizes, int n_in,
                              void* d_out, int out_size)
{
    const float* act = (const float*)d_in[0];
    float* out = (float*)d_out;

    dim3 grid((H_ + BAND - 1) / BAND, C_, N_);   // 19 x 16 x 32
    block_relu_kernel<<<grid, 224>>>(act, out);
}

// round 2
// speedup vs baseline: 1.1934x; 1.1934x over previous
#include <cuda_runtime.h>
#include <cuda_bf16.h>

// activation (N=32, C=16, H=224, W=224) fp32.
// c0-1 identity, c2-3 1x1 relu, c4-7 2x2 blocks, c8-11 4x4, c12-15 3x3.
#define HW4 12544   // 224*224/4 (float4 per image-channel)
#define W4  56      // 224/4     (float4 per row)
#define H_  224

// ---------- c0-3: identity / elementwise relu, pure streaming ----------
__global__ __launch_bounds__(256) void kA(const float4* __restrict__ in,
                                          float4* __restrict__ out)
{
    int i = blockIdx.x * 256 + threadIdx.x;          // exactly 32*4*HW4 threads
    int n   = i / (4 * HW4);
    int rem = i - n * (4 * HW4);
    int c   = rem / HW4;
    int off = rem - c * HW4;
    size_t g = (size_t)(n * 16 + c) * HW4 + off;
    float4 v = in[g];
    if (c >= 2) {
        v.x = (v.x >= 0.f) ? v.x : 0.f;
        v.y = (v.y >= 0.f) ? v.y : 0.f;
        v.z = (v.z >= 0.f) ? v.z : 0.f;
        v.w = (v.w >= 0.f) ? v.w : 0.f;
    }
    out[g] = v;
}

// ---------- c4-7: 2x2 blocks, two blocks per thread (2 rows x 1 float4) ----------
__global__ __launch_bounds__(256) void kB(const float4* __restrict__ in,
                                          float4* __restrict__ out)
{
    int i = blockIdx.x * 256 + threadIdx.x;          // exactly 32*4*6272 threads
    int n   = i / (4 * 6272);
    int rem = i - n * (4 * 6272);
    int c   = 4 + rem / 6272;
    int v   = rem % 6272;
    int rp  = v / W4;                                 // row-pair 0..111
    int f4  = v - rp * W4;                            // float4 col 0..55
    size_t i0 = (size_t)(n * 16 + c) * HW4 + (size_t)(2 * rp) * W4 + f4;
    size_t i1 = i0 + W4;

    float4 a = in[i0];
    float4 b = in[i1];
    // column sums (rows first), then columns ascending — matches reference order
    float cs0 = a.x + b.x, cs1 = a.y + b.y, cs2 = a.z + b.z, cs3 = a.w + b.w;
    float mL = ((cs0 + cs1) >= 0.f) ? 1.f : 0.f;
    float mR = ((cs2 + cs3) >= 0.f) ? 1.f : 0.f;
    a.x *= mL; a.y *= mL; a.z *= mR; a.w *= mR;
    b.x *= mL; b.y *= mL; b.z *= mR; b.w *= mR;
    out[i0] = a;
    out[i1] = b;
}

// ---------- c8-11: 4x4 blocks, one block per thread (4 rows x 1 float4) ----------
__global__ __launch_bounds__(256) void kC(const float4* __restrict__ in,
                                          float4* __restrict__ out)
{
    int i = blockIdx.x * 256 + threadIdx.x;          // exactly 32*4*3136 threads
    int n   = i / (4 * 3136);
    int rem = i - n * (4 * 3136);
    int c   = 8 + rem / 3136;
    int v   = rem % 3136;
    int rq  = v / W4;                                 // block-row 0..55
    int f4  = v - rq * W4;                            // float4 col 0..55
    size_t i0 = (size_t)(n * 16 + c) * HW4 + (size_t)(4 * rq) * W4 + f4;

    float4 r0 = in[i0];
    float4 r1 = in[i0 + W4];
    float4 r2 = in[i0 + 2 * W4];
    float4 r3 = in[i0 + 3 * W4];
    float cs0 = r0.x + r1.x + r2.x + r3.x;
    float cs1 = r0.y + r1.y + r2.y + r3.y;
    float cs2 = r0.z + r1.z + r2.z + r3.z;
    float cs3 = r0.w + r1.w + r2.w + r3.w;
    float m = ((cs0 + cs1 + cs2 + cs3) >= 0.f) ? 1.f : 0.f;
    r0.x *= m; r0.y *= m; r0.z *= m; r0.w *= m;
    r1.x *= m; r1.y *= m; r1.z *= m; r1.w *= m;
    r2.x *= m; r2.y *= m; r2.z *= m; r2.w *= m;
    r3.x *= m; r3.y *= m; r3.z *= m; r3.w *= m;
    out[i0]          = r0;
    out[i0 + W4]     = r1;
    out[i0 + 2 * W4] = r2;
    out[i0 + 3 * W4] = r3;
}

// ---------- c12-15: 3x3 blocks, four blocks per thread (3 rows x 3 float4 = 12 cols) ----------
// 224 = 3*74 + 2 -> 75 block-rows (last padded); 224 cols = 18.67 strips of 12 -> 19 strips.
__global__ __launch_bounds__(256) void kD(const float4* __restrict__ in,
                                          float4* __restrict__ out)
{
    int i = blockIdx.x * 256 + threadIdx.x;
    if (i >= 32 * 4 * 1425) return;                  // 75 block-rows * 19 strips
    int n   = i / (4 * 1425);
    int rem = i - n * (4 * 1425);
    int c   = 12 + rem / 1425;
    int v   = rem % 1425;
    int br  = v / 19;                                // block-row 0..74
    int s   = v - br * 19;                           // 12-col strip 0..18
    int r0  = br * 3;
    size_t base = (size_t)(n * 16 + c) * HW4;

    float4 val[3][3];
    #pragma unroll
    for (int r = 0; r < 3; r++) {
        int rr = r0 + r;
        bool rv = rr < H_;
        #pragma unroll
        for (int k = 0; k < 3; k++) {
            int fc = s * 3 + k;
            if (rv && fc < W4)
                val[r][k] = in[base + (size_t)rr * W4 + fc];
            else
                val[r][k] = make_float4(0.f, 0.f, 0.f, 0.f);   // zero padding
        }
    }

    // per-column sums over the 3 rows (rows first)
    float cs[12];
    #pragma unroll
    for (int k = 0; k < 3; k++) {
        cs[4 * k + 0] = val[0][k].x + val[1][k].x + val[2][k].x;
        cs[4 * k + 1] = val[0][k].y + val[1][k].y + val[2][k].y;
        cs[4 * k + 2] = val[0][k].z + val[1][k].z + val[2][k].z;
        cs[4 * k + 3] = val[0][k].w + val[1][k].w + val[2][k].w;
    }
    // strip is 12-aligned -> local col L belongs to group L/3; columns ascending
    float m[4];
    #pragma unroll
    for (int g = 0; g < 4; g++)
        m[g] = ((cs[3 * g] + cs[3 * g + 1] + cs[3 * g + 2]) >= 0.f) ? 1.f : 0.f;

    #pragma unroll
    for (int r = 0; r < 3; r++) {
        int rr = r0 + r;
        if (rr >= H_) break;
        #pragma unroll
        for (int k = 0; k < 3; k++) {
            int fc = s * 3 + k;
            if (fc < W4) {
                float4 t = val[r][k];
                int L = 4 * k;
                t.x *= m[(L + 0) / 3];
                t.y *= m[(L + 1) / 3];
                t.z *= m[(L + 2) / 3];
                t.w *= m[(L + 3) / 3];
                out[base + (size_t)rr * W4 + fc] = t;
            }
        }
    }
}

extern "C" void kernel_launch(void* const* d_in, const int* in_sizes, int n_in,
                              void* d_out, int out_size)
{
    const float4* in  = (const float4*)d_in[0];
    float4*       out = (float4*)d_out;

    kA<<<6272, 256>>>(in, out);   // c0-3:  1,605,632 float4 units
    kB<<<3136, 256>>>(in, out);   // c4-7:    802,816 units (2 f4 each)
    kC<<<1568, 256>>>(in, out);   // c8-11:   401,408 units (4 f4 each)
    kD<<< 713, 256>>>(in, out);   // c12-15:  182,400 units (9 f4 each)
}

// round 3
// speedup vs baseline: 1.3174x; 1.1039x over previous
#include <cuda_runtime.h>
#include <cuda_bf16.h>

// activation (N=32, C=16, H=224, W=224) fp32.
// c0-1 identity, c2-3 1x1 relu, c4-7 2x2 blocks, c8-11 4x4, c12-15 3x3.
#define HW4 12544   // 224*224/4 (float4 per image-channel)
#define W4  56      // 224/4
#define H_  224

// Per-image unit layout (heavy-first for load balance):
//   [0,      5700)  : 3x3 units  (4 ch * 1425, 9 float4 each)
//   [5700,  18244)  : 4x4 units  (4 ch * 3136, 4 float4 each)
//   [18244, 43332)  : 2x2 units  (4 ch * 6272, 2 float4 each)
//   [43332, 93508)  : elementwise units (4 ch * 12544, 1 float4 each)
#define SEG_D 5700
#define SEG_C 18244
#define SEG_B 43332
#define PER_N 93508
#define TOTAL (32 * PER_N)   // 2,992,256

__global__ __launch_bounds__(256) void block_relu_fused(
    const float4* __restrict__ in, float4* __restrict__ out)
{
    int i = blockIdx.x * 256 + threadIdx.x;
    if (i >= TOTAL) return;
    int n = i / PER_N;
    int u = i - n * PER_N;
    const size_t nbase = (size_t)n * 16 * HW4;

    if (u >= SEG_B) {
        // ---- c0-3: identity / elementwise relu ----
        int t   = u - SEG_B;
        int c   = t / HW4;
        int off = t - c * HW4;
        size_t g = nbase + (size_t)c * HW4 + off;
        float4 v = in[g];
        if (c >= 2) {
            v.x = (v.x >= 0.f) ? v.x : 0.f;
            v.y = (v.y >= 0.f) ? v.y : 0.f;
            v.z = (v.z >= 0.f) ? v.z : 0.f;
            v.w = (v.w >= 0.f) ? v.w : 0.f;
        }
        out[g] = v;
    } else if (u >= SEG_C) {
        // ---- c4-7: 2x2 blocks, two blocks per thread (2 rows x 1 float4) ----
        int t  = u - SEG_C;
        int c  = 4 + t / 6272;
        int v  = t % 6272;
        int rp = v / W4;
        int f4 = v - rp * W4;
        size_t i0 = nbase + (size_t)c * HW4 + (size_t)(2 * rp) * W4 + f4;
        size_t i1 = i0 + W4;

        float4 a = in[i0];
        float4 b = in[i1];
        float cs0 = a.x + b.x, cs1 = a.y + b.y, cs2 = a.z + b.z, cs3 = a.w + b.w;
        float mL = ((cs0 + cs1) >= 0.f) ? 1.f : 0.f;
        float mR = ((cs2 + cs3) >= 0.f) ? 1.f : 0.f;
        a.x *= mL; a.y *= mL; a.z *= mR; a.w *= mR;
        b.x *= mL; b.y *= mL; b.z *= mR; b.w *= mR;
        out[i0] = a;
        out[i1] = b;
    } else if (u >= SEG_D) {
        // ---- c8-11: 4x4 blocks, one block per thread (4 rows x 1 float4) ----
        int t  = u - SEG_D;
        int c  = 8 + t / 3136;
        int v  = t % 3136;
        int rq = v / W4;
        int f4 = v - rq * W4;
        size_t i0 = nbase + (size_t)c * HW4 + (size_t)(4 * rq) * W4 + f4;

        float4 r0 = in[i0];
        float4 r1 = in[i0 + W4];
        float4 r2 = in[i0 + 2 * W4];
        float4 r3 = in[i0 + 3 * W4];
        float cs0 = r0.x + r1.x + r2.x + r3.x;
        float cs1 = r0.y + r1.y + r2.y + r3.y;
        float cs2 = r0.z + r1.z + r2.z + r3.z;
        float cs3 = r0.w + r1.w + r2.w + r3.w;
        float m = ((cs0 + cs1 + cs2 + cs3) >= 0.f) ? 1.f : 0.f;
        r0.x *= m; r0.y *= m; r0.z *= m; r0.w *= m;
        r1.x *= m; r1.y *= m; r1.z *= m; r1.w *= m;
        r2.x *= m; r2.y *= m; r2.z *= m; r2.w *= m;
        r3.x *= m; r3.y *= m; r3.z *= m; r3.w *= m;
        out[i0]          = r0;
        out[i0 + W4]     = r1;
        out[i0 + 2 * W4] = r2;
        out[i0 + 3 * W4] = r3;
    } else {
        // ---- c12-15: 3x3 blocks, four blocks per thread (3 rows x 12 cols) ----
        int c  = 12 + u / 1425;
        int v  = u % 1425;
        int br = v / 19;              // block-row 0..74
        int s  = v - br * 19;         // 12-col strip 0..18
        int r0 = br * 3;
        size_t base = nbase + (size_t)c * HW4;

        float4 val[3][3];
        #pragma unroll
        for (int r = 0; r < 3; r++) {
            int rr = r0 + r;
            bool rv = rr < H_;
            #pragma unroll
            for (int k = 0; k < 3; k++) {
                int fc = s * 3 + k;
                if (rv && fc < W4)
                    val[r][k] = in[base + (size_t)rr * W4 + fc];
                else
                    val[r][k] = make_float4(0.f, 0.f, 0.f, 0.f);
            }
        }

        float cs[12];
        #pragma unroll
        for (int k = 0; k < 3; k++) {
            cs[4 * k + 0] = val[0][k].x + val[1][k].x + val[2][k].x;
            cs[4 * k + 1] = val[0][k].y + val[1][k].y + val[2][k].y;
            cs[4 * k + 2] = val[0][k].z + val[1][k].z + val[2][k].z;
            cs[4 * k + 3] = val[0][k].w + val[1][k].w + val[2][k].w;
        }
        float m[4];
        #pragma unroll
        for (int g = 0; g < 4; g++)
            m[g] = ((cs[3 * g] + cs[3 * g + 1] + cs[3 * g + 2]) >= 0.f) ? 1.f : 0.f;

        #pragma unroll
        for (int r = 0; r < 3; r++) {
            int rr = r0 + r;
            if (rr >= H_) break;
            #pragma unroll
            for (int k = 0; k < 3; k++) {
                int fc = s * 3 + k;
                if (fc < W4) {
                    float4 tv = val[r][k];
                    int L = 4 * k;
                    tv.x *= m[(L + 0) / 3];
                    tv.y *= m[(L + 1) / 3];
                    tv.z *= m[(L + 2) / 3];
                    tv.w *= m[(L + 3) / 3];
                    out[base + (size_t)rr * W4 + fc] = tv;
                }
            }
        }
    }
}

extern "C" void kernel_launch(void* const* d_in, const int* in_sizes, int n_in,
                              void* d_out, int out_size)
{
    const float4* in  = (const float4*)d_in[0];
    float4*       out = (float4*)d_out;
    block_relu_fused<<<(TOTAL + 255) / 256, 256>>>(in, out);  // 11,689 CTAs
}

// round 4
// speedup vs baseline: 1.4701x; 1.1159x over previous
#include <cuda_runtime.h>
#include <cuda_bf16.h>

// activation (N=32, C=16, H=224, W=224) fp32.
// c0-1 identity, c2-3 1x1 relu, c4-7 2x2, c8-11 4x4, c12-15 3x3.
#define HW4 12544   // float4 per image-channel
#define W4  56      // float4 per row
#define H_  224
#define Q_  3136    // HW4/4

// Per-image thread units (heavy-first):
//   [0,     5700) : 3x3 units   (4ch * 1425, 9 f4 each)
//   [5700, 18244) : 4x4 units   (4ch * 3136, 4 f4 each: rows 4q..4q+3 x 1 f4, one mask)
//   [18244,30788) : 2x2 units   (4ch * 3136, 4 f4 each: rows 4q..4q+3 x 1 f4, two masks)
//   [30788,43332) : elementwise (4ch * 3136, 4 f4 each, strided)
#define SEG_C 5700
#define SEG_B 18244
#define SEG_A 30788
#define PER_N 43332
#define TOTAL (32 * PER_N)   // 1,386,624

__global__ __launch_bounds__(256) void block_relu_fused(
    const float4* __restrict__ in, float4* __restrict__ out)
{
    int i = blockIdx.x * 256 + threadIdx.x;
    if (i >= TOTAL) return;
    int n = i / PER_N;
    int u = i - n * PER_N;
    const size_t nbase = (size_t)n * 16 * HW4;

    if (u >= SEG_A) {
        // ---- c0-3: identity / elementwise relu, 4 strided float4 per thread ----
        int t    = u - SEG_A;
        int c    = t / Q_;
        int off0 = t - c * Q_;
        size_t g = nbase + (size_t)c * HW4 + off0;
        float4 v0 = in[g];
        float4 v1 = in[g + Q_];
        float4 v2 = in[g + 2 * Q_];
        float4 v3 = in[g + 3 * Q_];
        if (c >= 2) {
            v0.x = fmaxf(v0.x, 0.f); v0.y = fmaxf(v0.y, 0.f); v0.z = fmaxf(v0.z, 0.f); v0.w = fmaxf(v0.w, 0.f);
            v1.x = fmaxf(v1.x, 0.f); v1.y = fmaxf(v1.y, 0.f); v1.z = fmaxf(v1.z, 0.f); v1.w = fmaxf(v1.w, 0.f);
            v2.x = fmaxf(v2.x, 0.f); v2.y = fmaxf(v2.y, 0.f); v2.z = fmaxf(v2.z, 0.f); v2.w = fmaxf(v2.w, 0.f);
            v3.x = fmaxf(v3.x, 0.f); v3.y = fmaxf(v3.y, 0.f); v3.z = fmaxf(v3.z, 0.f); v3.w = fmaxf(v3.w, 0.f);
        }
        out[g]          = v0;
        out[g + Q_]     = v1;
        out[g + 2 * Q_] = v2;
        out[g + 3 * Q_] = v3;
    } else if (u >= SEG_C) {
        // ---- c4-11: 4 rows x 1 float4 per thread ----
        // 4x4 channels: one mask over all 16; 2x2 channels: two masks (rows 0-1 / 2-3, cols xy / zw).
        bool is2x2 = (u >= SEG_B);
        int t  = u - (is2x2 ? SEG_B : SEG_C);
        int c  = (is2x2 ? 4 : 8) + t / Q_;
        int v  = t % Q_;
        int rq = v / W4;                   // 4-row group 0..55
        int f4 = v - rq * W4;
        size_t i0 = nbase + (size_t)c * HW4 + (size_t)(4 * rq) * W4 + f4;

        float4 r0 = in[i0];
        float4 r1 = in[i0 + W4];
        float4 r2 = in[i0 + 2 * W4];
        float4 r3 = in[i0 + 3 * W4];

        if (is2x2) {
            // top block-row: rows r0,r1 ; bottom: r2,r3
            float tx = r0.x + r1.x, ty = r0.y + r1.y, tz = r0.z + r1.z, tw = r0.w + r1.w;
            float bx = r2.x + r3.x, by = r2.y + r3.y, bz = r2.z + r3.z, bw = r2.w + r3.w;
            float mTL = ((tx + ty) >= 0.f) ? 1.f : 0.f;
            float mTR = ((tz + tw) >= 0.f) ? 1.f : 0.f;
            float mBL = ((bx + by) >= 0.f) ? 1.f : 0.f;
            float mBR = ((bz + bw) >= 0.f) ? 1.f : 0.f;
            r0.x *= mTL; r0.y *= mTL; r0.z *= mTR; r0.w *= mTR;
            r1.x *= mTL; r1.y *= mTL; r1.z *= mTR; r1.w *= mTR;
            r2.x *= mBL; r2.y *= mBL; r2.z *= mBR; r2.w *= mBR;
            r3.x *= mBL; r3.y *= mBL; r3.z *= mBR; r3.w *= mBR;
        } else {
            float cs0 = r0.x + r1.x + r2.x + r3.x;
            float cs1 = r0.y + r1.y + r2.y + r3.y;
            float cs2 = r0.z + r1.z + r2.z + r3.z;
            float cs3 = r0.w + r1.w + r2.w + r3.w;
            float m = ((cs0 + cs1 + cs2 + cs3) >= 0.f) ? 1.f : 0.f;
            r0.x *= m; r0.y *= m; r0.z *= m; r0.w *= m;
            r1.x *= m; r1.y *= m; r1.z *= m; r1.w *= m;
            r2.x *= m; r2.y *= m; r2.z *= m; r2.w *= m;
            r3.x *= m; r3.y *= m; r3.z *= m; r3.w *= m;
        }
        out[i0]          = r0;
        out[i0 + W4]     = r1;
        out[i0 + 2 * W4] = r2;
        out[i0 + 3 * W4] = r3;
    } else {
        // ---- c12-15: 3x3 blocks, four blocks per thread (3 rows x 12 cols) ----
        int c  = 12 + u / 1425;
        int v  = u % 1425;
        int br = v / 19;              // block-row 0..74
        int s  = v - br * 19;         // 12-col strip 0..18
        int r0 = br * 3;
        size_t base = nbase + (size_t)c * HW4;

        float4 val[3][3];
        #pragma unroll
        for (int r = 0; r < 3; r++) {
            int rr = r0 + r;
            bool rv = rr < H_;
            #pragma unroll
            for (int k = 0; k < 3; k++) {
                int fc = s * 3 + k;
                if (rv && fc < W4)
                    val[r][k] = in[base + (size_t)rr * W4 + fc];
                else
                    val[r][k] = make_float4(0.f, 0.f, 0.f, 0.f);
            }
        }

        float cs[12];
        #pragma unroll
        for (int k = 0; k < 3; k++) {
            cs[4 * k + 0] = val[0][k].x + val[1][k].x + val[2][k].x;
            cs[4 * k + 1] = val[0][k].y + val[1][k].y + val[2][k].y;
            cs[4 * k + 2] = val[0][k].z + val[1][k].z + val[2][k].z;
            cs[4 * k + 3] = val[0][k].w + val[1][k].w + val[2][k].w;
        }
        float m[4];
        #pragma unroll
        for (int g = 0; g < 4; g++)
            m[g] = ((cs[3 * g] + cs[3 * g + 1] + cs[3 * g + 2]) >= 0.f) ? 1.f : 0.f;

        #pragma unroll
        for (int r = 0; r < 3; r++) {
            int rr = r0 + r;
            if (rr >= H_) break;
            #pragma unroll
            for (int k = 0; k < 3; k++) {
                int fc = s * 3 + k;
                if (fc < W4) {
                    float4 tv = val[r][k];
                    int L = 4 * k;
                    tv.x *= m[(L + 0) / 3];
                    tv.y *= m[(L + 1) / 3];
                    tv.z *= m[(L + 2) / 3];
                    tv.w *= m[(L + 3) / 3];
                    out[base + (size_t)rr * W4 + fc] = tv;
                }
            }
        }
    }
}

extern "C" void kernel_launch(void* const* d_in, const int* in_sizes, int n_in,
                              void* d_out, int out_size)
{
    const float4* in  = (const float4*)d_in[0];
    float4*       out = (float4*)d_out;
    block_relu_fused<<<(TOTAL + 255) / 256, 256>>>(in, out);  // 5417 CTAs
}